// round 17
// baseline (speedup 1.0000x reference)
#include <cuda_runtime.h>

// loss = 0.5 * mean( (tw[b,j] * (output[b,j,hw] - target[b,j,hw]))^2 )
// B=256, J=17, HW=64*48=3072  ->  N = 13,369,344 floats, N4 = 3,342,336 float4
// tw has B*J = 4352 entries; each covers 768 consecutive float4s.
//
// Proven-best structure (R7 @ 15.1us) + known-trip-count loop:
//   1184 blocks (8/SM on 148 SMs, perfectly balanced) x 256 threads
//   N4 = 1184*256*11 + 8192  -> 11 unrolled trips + masked tail element.
// Plain float4 loads (L2 policy hints measured net-negative 3x), low regs,
// ~96% occupancy. Reduction: block partial -> 64-bit fixed-point atomicAdd
// (associative -> bitwise deterministic), last block finalizes.

#define N_ELEMS   13369344
#define N4        3342336
#define F4_PER_BJ 768
#define NBLOCKS   1184            // 148 * 8, balanced
#define NTHREADS  256
#define TRIPS     11              // full trips; tail = N4 - 1184*256*11 = 8192
#define STRIDE    (NBLOCKS * NTHREADS)   // 303104

__device__ unsigned long long g_sum;    // zero-init; reset via atomicExch each call
__device__ unsigned int       g_count;  // zero-init; reset by last block each call

__global__ __launch_bounds__(NTHREADS) void wmse_onepass_kernel(
    const float4* __restrict__ out4,
    const float4* __restrict__ tgt4,
    const float*  __restrict__ tw,
    float*        __restrict__ result)
{
    const int tid  = threadIdx.x;
    const int base = blockIdx.x * NTHREADS + tid;

    float acc = 0.0f;
    #pragma unroll 4
    for (int k = 0; k < TRIPS; k++) {
        const int i = base + k * STRIDE;          // always < N4, no check
        const float4 o = out4[i];
        const float4 t = tgt4[i];
        const float  w = tw[i / F4_PER_BJ];       // 4352 entries, L1/L2-resident
        float d0 = (o.x - t.x) * w;
        float d1 = (o.y - t.y) * w;
        float d2 = (o.z - t.z) * w;
        float d3 = (o.w - t.w) * w;
        acc += d0 * d0 + d1 * d1 + d2 * d2 + d3 * d3;
    }
    // masked tail: first 8192 threads take one extra element
    {
        const int i = base + TRIPS * STRIDE;
        if (i < N4) {
            const float4 o = out4[i];
            const float4 t = tgt4[i];
            const float  w = tw[i / F4_PER_BJ];
            float d0 = (o.x - t.x) * w;
            float d1 = (o.y - t.y) * w;
            float d2 = (o.z - t.z) * w;
            float d3 = (o.w - t.w) * w;
            acc += d0 * d0 + d1 * d1 + d2 * d2 + d3 * d3;
        }
    }

    // intra-block reduce (float, fixed order)
    #pragma unroll
    for (int off = 16; off > 0; off >>= 1)
        acc += __shfl_down_sync(0xFFFFFFFFu, acc, off);

    __shared__ float warp_sums[NTHREADS / 32];
    if ((tid & 31) == 0) warp_sums[tid >> 5] = acc;
    __syncthreads();

    __shared__ bool is_last;
    if (tid == 0) {
        float v = 0.0f;
        #pragma unroll
        for (int w = 0; w < NTHREADS / 32; w++) v += warp_sums[w];

        // fixed-point (2^40) contribution -> associative integer accumulation
        unsigned long long q =
            (unsigned long long)((double)v * 1099511627776.0);  // * 2^40
        atomicAdd(&g_sum, q);
        __threadfence();  // order value-add before counter-add (cross-addr)
        unsigned int prev = atomicAdd(&g_count, 1u);
        is_last = (prev == (unsigned int)(NBLOCKS - 1));
    }
    __syncthreads();

    if (is_last && tid == 0) {
        unsigned long long total_q = atomicExch(&g_sum, 0ULL);
        double total = (double)total_q * 9.094947017729282379e-13;  // * 2^-40
        result[0] = (float)(0.5 * total / (double)N_ELEMS);
        g_count = 0;   // safe: this block was the final incrementer
    }
}

extern "C" void kernel_launch(void* const* d_in, const int* in_sizes, int n_in,
                              void* d_out, int out_size)
{
    const float4* out4 = (const float4*)d_in[0];
    const float4* tgt4 = (const float4*)d_in[1];
    const float*  tw   = (const float*)d_in[2];
    float* out = (float*)d_out;

    wmse_onepass_kernel<<<NBLOCKS, NTHREADS>>>(out4, tgt4, tw, out);
}